// round 15
// baseline (speedup 1.0000x reference)
#include <cuda_runtime.h>
#include <cuda_fp16.h>
#include <stdint.h>

#define NN 50000
#define NE 800000
#define D  96
#define NC 16
#define ST (NN*D)        // 4,800,000
#define SCB 49           // scan blocks: 49 * 1024 >= NN

// ---------------- scratch (static device globals; no allocation) ----------
// X split: XA = columns 0-63 (128B/row, line-aligned), XB = columns 64-95 (64B/row).
__device__ __align__(256) __half g_XA[NN * 64];
__device__ __align__(256) __half g_XB[NN * 32];
__device__ __align__(16) float g_Y[ST];   // aggregation output (iI applied)
__device__ __align__(16) float g_Z[NN * NC]; // X @ W2 (pre-aggregation head)
__device__ int   g_cO[NN];
__device__ int   g_cI[NN];
__device__ float g_iO[NN];
__device__ float g_iI[NN];
__device__ int   g_off[NN + 1];           // CSR offsets by dst
__device__ int   g_cur[NN];               // fill cursors
__device__ int   g_part[SCB];             // per-block totals
__device__ int   g_partx[SCB];            // exclusive scan of totals
__device__ uint2 g_ep[NE];                // packed (src, folded-weight-bits) by dst

// ---------------- threefry2x32-20 (matches JAX) ----------------------------
__device__ __host__ __forceinline__ void tf2x32(uint32_t k0, uint32_t k1,
                                                uint32_t& x0, uint32_t& x1) {
    uint32_t k2 = k0 ^ k1 ^ 0x1BD11BDAu;
    x0 += k0; x1 += k1;
#define TF_R(r) { x0 += x1; x1 = (x1 << (r)) | (x1 >> (32 - (r))); x1 ^= x0; }
    TF_R(13) TF_R(15) TF_R(26) TF_R(6)   x0 += k1; x1 += k2 + 1u;
    TF_R(17) TF_R(29) TF_R(16) TF_R(24)  x0 += k2; x1 += k0 + 2u;
    TF_R(13) TF_R(15) TF_R(26) TF_R(6)   x0 += k0; x1 += k1 + 3u;
    TF_R(17) TF_R(29) TF_R(16) TF_R(24)  x0 += k1; x1 += k2 + 4u;
    TF_R(13) TF_R(15) TF_R(26) TF_R(6)   x0 += k2; x1 += k0 + 5u;
#undef TF_R
}

// keep ⇔ msb(out0 ^ out1) == 0, counter (0, idx)  [JAX partitionable threefry]
__device__ __forceinline__ bool keep_bit(uint32_t k0, uint32_t k1, uint32_t idx) {
    uint32_t x0 = 0u, x1 = idx;
    tf2x32(k0, k1, x0, x1);
    return (x0 ^ x1) < 0x80000000u;
}

// ---------------- degree kernels -------------------------------------------
__global__ void k_zero() {
    int i = blockIdx.x * blockDim.x + threadIdx.x;
    if (i < NN) { g_cO[i] = 0; g_cI[i] = 0; }
}

__global__ void k_count(const int* __restrict__ src, const int* __restrict__ dst) {
    int e = blockIdx.x * blockDim.x + threadIdx.x;
    if (e < NE) {
        atomicAdd(&g_cO[src[e]], 1);
        atomicAdd(&g_cI[dst[e]], 1);
    }
}

__global__ void k_fin() {
    int i = blockIdx.x * blockDim.x + threadIdx.x;
    if (i < NN) {
        g_iO[i] = rsqrtf((float)max(g_cO[i], 1));
        g_iI[i] = rsqrtf((float)max(g_cI[i], 1));
    }
}

// ---------------- CSR build: 3-phase multi-block scan -----------------------
__global__ void k_scanA() {
    __shared__ int sh[256];
    int t = threadIdx.x;
    int base = blockIdx.x * 1024 + t * 4;
    int v[4], s = 0;
#pragma unroll
    for (int j = 0; j < 4; j++) {
        v[j] = (base + j < NN) ? g_cI[base + j] : 0;
        s += v[j];
    }
    sh[t] = s;
    __syncthreads();
#pragma unroll
    for (int off = 1; off < 256; off <<= 1) {
        int x = (t >= off) ? sh[t - off] : 0;
        __syncthreads();
        sh[t] += x;
        __syncthreads();
    }
    int run = sh[t] - s;   // exclusive prefix within block
#pragma unroll
    for (int j = 0; j < 4; j++) {
        if (base + j < NN) g_off[base + j] = run;
        run += v[j];
    }
    if (t == 255) g_part[blockIdx.x] = sh[255];
}

__global__ void k_scanB() {
    int run = 0;
#pragma unroll
    for (int i = 0; i < SCB; i++) { g_partx[i] = run; run += g_part[i]; }
}

__global__ void k_scanC() {
    int t = threadIdx.x;
    int base = blockIdx.x * 1024 + t * 4;
    int add = g_partx[blockIdx.x];
#pragma unroll
    for (int j = 0; j < 4; j++) {
        int i = base + j;
        if (i < NN) {
            int o = g_off[i] + add;
            g_off[i] = o;
            g_cur[i] = o;
        }
    }
    if (blockIdx.x == 0 && t == 0) g_off[NN] = NE;
}

// Fold dropout 1/(1-p)=2 and D_out^-1/2 of the source into the edge weight.
__global__ void k_fill(const int* __restrict__ src, const int* __restrict__ dst,
                       const float* __restrict__ ew) {
    int e = blockIdx.x * blockDim.x + threadIdx.x;
    if (e < NE) {
        int d = dst[e];
        int s = src[e];
        float w = ew[e] * 2.0f * g_iO[s];
        int slot = atomicAdd(&g_cur[d], 1);
        g_ep[slot] = make_uint2((uint32_t)s, __float_as_uint(w));
    }
}

// ---------------- layer-0 dropout on the input features -> split fp16 -------
__global__ void k_prep(const float* __restrict__ hin, uint32_t k0, uint32_t k1) {
    int t = blockIdx.x * blockDim.x + threadIdx.x;
    if (t >= ST / 4) return;
    int row = t / 24;              // 24 threads per 96-wide row
    int col = (t % 24) * 4;
    int j = row * 96 + col;        // logical index for RNG + input
    float4 a = *(const float4*)(hin + j);
    float v[4] = {a.x, a.y, a.z, a.w};
#pragma unroll
    for (int i = 0; i < 4; i++) {
        if (!keep_bit(k0, k1, (uint32_t)(j + i))) v[i] = 0.0f;
    }
    __half2 h0 = __floats2half2_rn(v[0], v[1]);
    __half2 h1 = __floats2half2_rn(v[2], v[3]);
    uint2 pk;
    pk.x = *(uint32_t*)&h0;
    pk.y = *(uint32_t*)&h1;
    if (col < 64) *(uint2*)(g_XA + row * 64 + col) = pk;
    else          *(uint2*)(g_XB + row * 32 + (col - 64)) = pk;
}

// ---------------- aggregation: warp per dst node (split fp16 gather) --------
// XA row = 32 words = one 128B line; XB row = 16 words = one 64B sector.
// Lane L: accA = word L of XA; accB = word (L&15) of XB, half-warps own
// different edges for the B load, combined by one shuffle at the end.
__global__ void k_agg() {
    int warp = (blockIdx.x * blockDim.x + threadIdx.x) >> 5;
    if (warp >= NN) return;
    int lane = threadIdx.x & 31;
    int l16 = lane & 15;
    bool lo = lane < 16;
    const uint32_t* XA32 = (const uint32_t*)g_XA;  // 32 words per row
    const uint32_t* XB32 = (const uint32_t*)g_XB;  // 16 words per row
    int beg = g_off[warp], end = g_off[warp + 1];
    __half2 accA = __float2half2_rn(0.f);
    __half2 accB = __float2half2_rn(0.f);
    int i = beg;
    for (; i + 2 <= end; i += 2) {
        uint2 p0 = g_ep[i], p1 = g_ep[i + 1];
        int r0 = (int)p0.x, r1 = (int)p1.x;
        __half2 w0 = __float2half2_rn(__uint_as_float(p0.y));
        __half2 w1 = __float2half2_rn(__uint_as_float(p1.y));
        uint32_t uA0 = XA32[r0 * 32 + lane];
        uint32_t uB  = XB32[(lo ? r0 : r1) * 16 + l16];
        uint32_t uA1 = XA32[r1 * 32 + lane];
        accA = __hfma2(w0, *(__half2*)&uA0, accA);
        accB = __hfma2(lo ? w0 : w1, *(__half2*)&uB, accB);
        accA = __hfma2(w1, *(__half2*)&uA1, accA);
    }
    if (i < end) {
        uint2 p = g_ep[i];
        int r = (int)p.x;
        __half2 w = __float2half2_rn(__uint_as_float(p.y));
        uint32_t uA = XA32[r * 32 + lane];
        accA = __hfma2(w, *(__half2*)&uA, accA);
        if (lo) {
            uint32_t uB = XB32[r * 16 + l16];
            accB = __hfma2(w, *(__half2*)&uB, accB);
        }
    }
    float2 fA = __half22float2(accA);
    float2 fB = __half22float2(accB);
    fB.x += __shfl_xor_sync(0xffffffffu, fB.x, 16);
    fB.y += __shfl_xor_sync(0xffffffffu, fB.y, 16);
    float sc = g_iI[warp];
    float2* y = (float2*)(g_Y + warp * D);   // 48 float2 per row
    y[lane] = make_float2(fA.x * sc, fA.y * sc);
    if (lo) y[32 + l16] = make_float2(fB.x * sc, fB.y * sc);
}

// ------- GEMM 96x96 + bias + relu + FUSED next-layer dropout -> split fp16 --
__global__ void k_gemm96(const float* __restrict__ W, const float* __restrict__ b,
                         uint32_t k0, uint32_t k1) {
    __shared__ float rows[8][8][96];   // 24.5 KB
    int tid = threadIdx.x, wid = tid >> 5, lane = tid & 31;
    int base = blockIdx.x * 64 + wid * 8;
#pragma unroll
    for (int j = 0; j < 8; j++) {
        int n = base + j;
        if (n < NN) {
            const float* yr = g_Y + n * 96;
            rows[wid][j][lane]      = yr[lane];
            rows[wid][j][lane + 32] = yr[lane + 32];
            rows[wid][j][lane + 64] = yr[lane + 64];
        }
    }
    float b0 = __ldg(b + lane), b1 = __ldg(b + lane + 32), b2 = __ldg(b + lane + 64);
    float acc[8][3];
#pragma unroll
    for (int j = 0; j < 8; j++) { acc[j][0] = b0; acc[j][1] = b1; acc[j][2] = b2; }
    __syncwarp();
#pragma unroll 4
    for (int k = 0; k < 96; k++) {
        float w0 = __ldg(W + k * 96 + lane);
        float w1 = __ldg(W + k * 96 + lane + 32);
        float w2 = __ldg(W + k * 96 + lane + 64);
#pragma unroll
        for (int j = 0; j < 8; j++) {
            float r = rows[wid][j][k];
            acc[j][0] += r * w0; acc[j][1] += r * w1; acc[j][2] += r * w2;
        }
    }
#pragma unroll
    for (int j = 0; j < 8; j++) {
        int n = base + j;
        if (n < NN) {
            // cols 0-63 -> XA, cols 64-95 -> XB
#pragma unroll
            for (int c = 0; c < 3; c++) {
                int col = lane + c * 32;
                float val = fmaxf(acc[j][c], 0.f);
                bool kp = keep_bit(k0, k1, (uint32_t)(n * 96 + col));
                __half hv = __float2half_rn(kp ? val : 0.0f);
                if (c < 2) g_XA[n * 64 + col] = hv;
                else       g_XB[n * 32 + (col - 64)] = hv;
            }
        }
    }
}

// ---------------- head GEMM first: Z = X @ W2 (96 -> 16, no bias) -----------
__global__ void k_gemmZ(const float* __restrict__ W) {
    __shared__ float Ws[96 * 16];
    __shared__ float rows[8][2][96];
    int tid = threadIdx.x, wid = tid >> 5, lane = tid & 31;
    for (int i = tid; i < 96 * 16; i += 256) Ws[i] = W[i];
    int h = lane >> 4, c = lane & 15;
    int n = blockIdx.x * 16 + wid * 2 + h;
    for (int k = c; k < 96; k += 16) {
        float v = (k < 64) ? __half2float(g_XA[n * 64 + k])
                           : __half2float(g_XB[n * 32 + (k - 64)]);
        rows[wid][h][k] = v;
    }
    __syncthreads();
    float acc = 0.f;
#pragma unroll 8
    for (int k = 0; k < 96; k++) acc += rows[wid][h][k] * Ws[k * 16 + c];
    g_Z[n * 16 + c] = acc;
}

// ------- final aggregation in 16-dim + iI + bias + log_softmax --------------
__global__ void k_agg16(const float* __restrict__ b, float* __restrict__ out) {
    int gtid = blockIdx.x * blockDim.x + threadIdx.x;
    int node = gtid >> 4;
    if (node >= NN) return;
    int c = gtid & 15;
    int beg = g_off[node], end = g_off[node + 1];
    float acc = 0.f;
    int i = beg;
    for (; i + 2 <= end; i += 2) {
        uint2 p0 = g_ep[i], p1 = g_ep[i + 1];
        float z0 = g_Z[(int)p0.x * 16 + c];
        float z1 = g_Z[(int)p1.x * 16 + c];
        acc += __uint_as_float(p0.y) * z0;
        acc += __uint_as_float(p1.y) * z1;
    }
    if (i < end) {
        uint2 p = g_ep[i];
        acc += __uint_as_float(p.y) * g_Z[(int)p.x * 16 + c];
    }
    acc = acc * g_iI[node] + __ldg(b + c);
    float m = acc;
#pragma unroll
    for (int o = 8; o; o >>= 1) m = fmaxf(m, __shfl_xor_sync(0xffffffffu, m, o, 16));
    float e = expf(acc - m);
    float ssum = e;
#pragma unroll
    for (int o = 8; o; o >>= 1) ssum += __shfl_xor_sync(0xffffffffu, ssum, o, 16);
    out[node * 16 + c] = acc - m - logf(ssum);
}

// ---------------- launch ----------------------------------------------------
extern "C" void kernel_launch(void* const* d_in, const int* in_sizes, int n_in,
                              void* d_out, int out_size) {
    const float* feat = (const float*)d_in[0];
    const float* ew   = (const float*)d_in[1];
    const int*   src  = (const int*)  d_in[2];
    const int*   dst  = (const int*)  d_in[3];
    const float* W0   = (const float*)d_in[4];
    const float* b0   = (const float*)d_in[5];
    const float* W1   = (const float*)d_in[6];
    const float* b1   = (const float*)d_in[7];
    const float* W2   = (const float*)d_in[8];
    const float* b2   = (const float*)d_in[9];
    float* out = (float*)d_out;

    // layer dropout keys: fold_in(key(42), l) = threefry((0,42), (0,l))
    uint32_t lk0[3], lk1[3];
    for (int l = 0; l < 3; l++) {
        uint32_t a = 0u, b = (uint32_t)l;
        tf2x32(0u, 42u, a, b);
        lk0[l] = a; lk1[l] = b;
    }

    const int TPB = 256;
    int nb_n = (NN + TPB - 1) / TPB;
    int nb_e = (NE + TPB - 1) / TPB;
    int nb_p = (ST / 4 + TPB - 1) / TPB;   // 1,200,000 / 256
    int nb_a = (NN * 32 + TPB - 1) / TPB;  // warp per node -> 6250
    int nb_g = (NN + 63) / 64;             // 782
    int nb_z = (NN + 15) / 16;             // 3125
    int nb_a16 = (NN * 16 + TPB - 1) / TPB;// 3125

    // graph preprocessing (reused by all 3 layers)
    k_zero<<<nb_n, TPB>>>();
    k_count<<<nb_e, TPB>>>(src, dst);
    k_fin<<<nb_n, TPB>>>();
    k_scanA<<<SCB, 256>>>();
    k_scanB<<<1, 1>>>();
    k_scanC<<<SCB, 256>>>();
    k_fill<<<nb_e, TPB>>>(src, dst, ew);

    // layer 0: dropout(feat) -> X ; agg ; gemm(W0) with fused dropout(key 1)
    k_prep<<<nb_p, TPB>>>(feat, lk0[0], lk1[0]);
    k_agg<<<nb_a, TPB>>>();
    k_gemm96<<<nb_g, TPB>>>(W0, b0, lk0[1], lk1[1]);
    // layer 1: agg ; gemm(W1) with fused dropout(key 2)
    k_agg<<<nb_a, TPB>>>();
    k_gemm96<<<nb_g, TPB>>>(W1, b1, lk0[2], lk1[2]);
    // layer 2 (head, reordered): Z = X @ W2 first, then 16-dim aggregation
    k_gemmZ<<<nb_z, TPB>>>(W2);
    k_agg16<<<nb_a16, TPB>>>(b2, out);
}

// round 16
// speedup vs baseline: 1.4920x; 1.4920x over previous
#include <cuda_runtime.h>
#include <cuda_fp16.h>
#include <stdint.h>

#define NN 50000
#define NE 800000
#define D  96
#define NC 16
#define ST (NN*D)        // 4,800,000
#define SCB 49           // scan blocks: 49 * 1024 >= NN

// ---------------- scratch (static device globals; no allocation) ----------
__device__ __align__(16) __half g_Xh[ST]; // dropout-masked layer input (fp16)
__device__ __align__(16) float g_Y[ST];   // aggregation output (iI applied)
__device__ __align__(16) float g_Z[NN * NC]; // X @ W2 (pre-aggregation head)
__device__ int   g_cO[NN];
__device__ int   g_cI[NN];
__device__ float g_iO[NN];
__device__ float g_iI[NN];
__device__ int   g_off[NN + 1];           // CSR offsets by dst
__device__ int   g_cur[NN];               // fill cursors
__device__ int   g_part[SCB];             // per-block totals
__device__ int   g_partx[SCB];            // exclusive scan of totals
__device__ uint2 g_ep[NE];                // packed (src, folded-weight-bits) by dst

// ---------------- threefry2x32-20 (matches JAX) ----------------------------
__device__ __host__ __forceinline__ void tf2x32(uint32_t k0, uint32_t k1,
                                                uint32_t& x0, uint32_t& x1) {
    uint32_t k2 = k0 ^ k1 ^ 0x1BD11BDAu;
    x0 += k0; x1 += k1;
#define TF_R(r) { x0 += x1; x1 = (x1 << (r)) | (x1 >> (32 - (r))); x1 ^= x0; }
    TF_R(13) TF_R(15) TF_R(26) TF_R(6)   x0 += k1; x1 += k2 + 1u;
    TF_R(17) TF_R(29) TF_R(16) TF_R(24)  x0 += k2; x1 += k0 + 2u;
    TF_R(13) TF_R(15) TF_R(26) TF_R(6)   x0 += k0; x1 += k1 + 3u;
    TF_R(17) TF_R(29) TF_R(16) TF_R(24)  x0 += k1; x1 += k2 + 4u;
    TF_R(13) TF_R(15) TF_R(26) TF_R(6)   x0 += k2; x1 += k0 + 5u;
#undef TF_R
}

// keep ⇔ msb(out0 ^ out1) == 0, counter (0, idx)  [JAX partitionable threefry]
__device__ __forceinline__ bool keep_bit(uint32_t k0, uint32_t k1, uint32_t idx) {
    uint32_t x0 = 0u, x1 = idx;
    tf2x32(k0, k1, x0, x1);
    return (x0 ^ x1) < 0x80000000u;
}

// ---------------- degree kernels -------------------------------------------
__global__ void k_zero() {
    int i = blockIdx.x * blockDim.x + threadIdx.x;
    if (i < NN) { g_cO[i] = 0; g_cI[i] = 0; }
}

__global__ void k_count(const int* __restrict__ src, const int* __restrict__ dst) {
    int e = blockIdx.x * blockDim.x + threadIdx.x;
    if (e < NE) {
        atomicAdd(&g_cO[src[e]], 1);
        atomicAdd(&g_cI[dst[e]], 1);
    }
}

// ---------------- CSR build: 3-phase multi-block scan (+ rsqrt fold) --------
__global__ void k_scanA() {
    __shared__ int sh[256];
    int t = threadIdx.x;
    int base = blockIdx.x * 1024 + t * 4;
    int v[4], s = 0;
#pragma unroll
    for (int j = 0; j < 4; j++) {
        int idx = base + j;
        if (idx < NN) {
            v[j] = g_cI[idx];
            g_iI[idx] = rsqrtf((float)max(v[j], 1));
            g_iO[idx] = rsqrtf((float)max(g_cO[idx], 1));
        } else v[j] = 0;
        s += v[j];
    }
    sh[t] = s;
    __syncthreads();
#pragma unroll
    for (int off = 1; off < 256; off <<= 1) {
        int x = (t >= off) ? sh[t - off] : 0;
        __syncthreads();
        sh[t] += x;
        __syncthreads();
    }
    int run = sh[t] - s;   // exclusive prefix within block
#pragma unroll
    for (int j = 0; j < 4; j++) {
        if (base + j < NN) g_off[base + j] = run;
        run += v[j];
    }
    if (t == 255) g_part[blockIdx.x] = sh[255];
}

__global__ void k_scanB() {
    int run = 0;
#pragma unroll
    for (int i = 0; i < SCB; i++) { g_partx[i] = run; run += g_part[i]; }
}

__global__ void k_scanC() {
    int t = threadIdx.x;
    int base = blockIdx.x * 1024 + t * 4;
    int add = g_partx[blockIdx.x];
#pragma unroll
    for (int j = 0; j < 4; j++) {
        int i = base + j;
        if (i < NN) {
            int o = g_off[i] + add;
            g_off[i] = o;
            g_cur[i] = o;
        }
    }
    if (blockIdx.x == 0 && t == 0) g_off[NN] = NE;
}

// Fold dropout 1/(1-p)=2 and D_out^-1/2 of the source into the edge weight.
__global__ void k_fill(const int* __restrict__ src, const int* __restrict__ dst,
                       const float* __restrict__ ew) {
    int e = blockIdx.x * blockDim.x + threadIdx.x;
    if (e < NE) {
        int d = dst[e];
        int s = src[e];
        float w = ew[e] * 2.0f * g_iO[s];
        int slot = atomicAdd(&g_cur[d], 1);
        g_ep[slot] = make_uint2((uint32_t)s, __float_as_uint(w));
    }
}

// ---------------- layer-0 dropout on the input features -> fp16 -------------
__global__ void k_prep(const float* __restrict__ hin, uint32_t k0, uint32_t k1) {
    int t = blockIdx.x * blockDim.x + threadIdx.x;
    if (t >= ST / 4) return;
    int j = t * 4;
    float4 a = *(const float4*)(hin + j);
    float v[4] = {a.x, a.y, a.z, a.w};
#pragma unroll
    for (int i = 0; i < 4; i++) {
        if (!keep_bit(k0, k1, (uint32_t)(j + i))) v[i] = 0.0f;
    }
    __half2 h0 = __floats2half2_rn(v[0], v[1]);
    __half2 h1 = __floats2half2_rn(v[2], v[3]);
    uint2 pk;
    pk.x = *(uint32_t*)&h0;
    pk.y = *(uint32_t*)&h1;
    *(uint2*)(g_Xh + j) = pk;
}

// ---------------- aggregation: warp per dst node (fp16 gather + HFMA2) ------
// Row = 48 uint32 words. Per 2 edges: 3 fully-active warp loads. The next
// iteration's g_ep pair is prefetched before the HFMA chain (sw pipelining).
__global__ void k_agg() {
    int warp = (blockIdx.x * blockDim.x + threadIdx.x) >> 5;
    if (warp >= NN) return;
    int lane = threadIdx.x & 31;
    int l16 = lane & 15;
    bool lo = lane < 16;
    const uint32_t* X32 = (const uint32_t*)g_Xh;   // 48 words per row
    int beg = g_off[warp], end = g_off[warp + 1];
    __half2 accA = __float2half2_rn(0.f);
    __half2 accB = __float2half2_rn(0.f);
    int i = beg;
    uint2 p0, p1;
    if (i + 2 <= end) { p0 = g_ep[i]; p1 = g_ep[i + 1]; }
    while (i + 2 <= end) {
        int r0 = (int)p0.x * 48, r1 = (int)p1.x * 48;
        uint32_t uA0 = X32[r0 + lane];                   // edge0 words 0-31
        uint32_t uB  = X32[(lo ? r0 : r1) + 32 + l16];   // words 32-47 split
        uint32_t uA1 = X32[r1 + lane];                   // edge1 words 0-31
        __half2 w0 = __float2half2_rn(__uint_as_float(p0.y));
        __half2 w1 = __float2half2_rn(__uint_as_float(p1.y));
        i += 2;
        if (i + 2 <= end) { p0 = g_ep[i]; p1 = g_ep[i + 1]; }  // prefetch next
        accA = __hfma2(w0, *(__half2*)&uA0, accA);
        accB = __hfma2(lo ? w0 : w1, *(__half2*)&uB, accB);
        accA = __hfma2(w1, *(__half2*)&uA1, accA);
    }
    if (i < end) {
        uint2 p = g_ep[i];
        int r = (int)p.x * 48;
        __half2 w = __float2half2_rn(__uint_as_float(p.y));
        uint32_t uA = X32[r + lane];
        accA = __hfma2(w, *(__half2*)&uA, accA);
        if (lo) {
            uint32_t uB = X32[r + 32 + l16];
            accB = __hfma2(w, *(__half2*)&uB, accB);
        }
    }
    float2 fA = __half22float2(accA);
    float2 fB = __half22float2(accB);
    fB.x += __shfl_xor_sync(0xffffffffu, fB.x, 16);
    fB.y += __shfl_xor_sync(0xffffffffu, fB.y, 16);
    float sc = g_iI[warp];
    float2* y = (float2*)(g_Y + warp * D);   // 48 float2 per row
    y[lane] = make_float2(fA.x * sc, fA.y * sc);
    if (lo) y[32 + l16] = make_float2(fB.x * sc, fB.y * sc);
}

// ------- GEMM 96x96 + bias + relu + FUSED next-layer dropout -> fp16 X ------
__global__ void k_gemm96(const float* __restrict__ W, const float* __restrict__ b,
                         uint32_t k0, uint32_t k1) {
    __shared__ float rows[8][8][96];   // 24.5 KB
    int tid = threadIdx.x, wid = tid >> 5, lane = tid & 31;
    int base = blockIdx.x * 64 + wid * 8;
#pragma unroll
    for (int j = 0; j < 8; j++) {
        int n = base + j;
        if (n < NN) {
            const float* yr = g_Y + n * 96;
            rows[wid][j][lane]      = yr[lane];
            rows[wid][j][lane + 32] = yr[lane + 32];
            rows[wid][j][lane + 64] = yr[lane + 64];
        }
    }
    float b0 = __ldg(b + lane), b1 = __ldg(b + lane + 32), b2 = __ldg(b + lane + 64);
    float acc[8][3];
#pragma unroll
    for (int j = 0; j < 8; j++) { acc[j][0] = b0; acc[j][1] = b1; acc[j][2] = b2; }
    __syncwarp();
#pragma unroll 4
    for (int k = 0; k < 96; k++) {
        float w0 = __ldg(W + k * 96 + lane);
        float w1 = __ldg(W + k * 96 + lane + 32);
        float w2 = __ldg(W + k * 96 + lane + 64);
#pragma unroll
        for (int j = 0; j < 8; j++) {
            float r = rows[wid][j][k];
            acc[j][0] += r * w0; acc[j][1] += r * w1; acc[j][2] += r * w2;
        }
    }
#pragma unroll
    for (int j = 0; j < 8; j++) {
        int n = base + j;
        if (n < NN) {
            __half* o = g_Xh + n * 96;
#pragma unroll
            for (int c = 0; c < 3; c++) {
                int col = lane + c * 32;
                float val = fmaxf(acc[j][c], 0.f);
                bool kp = keep_bit(k0, k1, (uint32_t)(n * 96 + col));
                o[col] = __float2half_rn(kp ? val : 0.0f);
            }
        }
    }
}

// ---------------- head GEMM first: Z = X @ W2 (96 -> 16, no bias) -----------
__global__ void k_gemmZ(const float* __restrict__ W) {
    __shared__ float Ws[96 * 16];
    __shared__ float rows[8][2][96];
    int tid = threadIdx.x, wid = tid >> 5, lane = tid & 31;
    for (int i = tid; i < 96 * 16; i += 256) Ws[i] = W[i];
    int h = lane >> 4, c = lane & 15;
    int n = blockIdx.x * 16 + wid * 2 + h;
    const __half* xr = g_Xh + n * 96;
    for (int k = c; k < 96; k += 16) rows[wid][h][k] = __half2float(xr[k]);
    __syncthreads();
    float acc = 0.f;
#pragma unroll 8
    for (int k = 0; k < 96; k++) acc += rows[wid][h][k] * Ws[k * 16 + c];
    g_Z[n * 16 + c] = acc;
}

// ------- final aggregation in 16-dim + iI + bias + log_softmax --------------
__global__ void k_agg16(const float* __restrict__ b, float* __restrict__ out) {
    int gtid = blockIdx.x * blockDim.x + threadIdx.x;
    int node = gtid >> 4;
    if (node >= NN) return;
    int c = gtid & 15;
    int beg = g_off[node], end = g_off[node + 1];
    float acc = 0.f;
    int i = beg;
    for (; i + 2 <= end; i += 2) {
        uint2 p0 = g_ep[i], p1 = g_ep[i + 1];
        float z0 = g_Z[(int)p0.x * 16 + c];
        float z1 = g_Z[(int)p1.x * 16 + c];
        acc += __uint_as_float(p0.y) * z0;
        acc += __uint_as_float(p1.y) * z1;
    }
    if (i < end) {
        uint2 p = g_ep[i];
        acc += __uint_as_float(p.y) * g_Z[(int)p.x * 16 + c];
    }
    acc = acc * g_iI[node] + __ldg(b + c);
    float m = acc;
#pragma unroll
    for (int o = 8; o; o >>= 1) m = fmaxf(m, __shfl_xor_sync(0xffffffffu, m, o, 16));
    float e = expf(acc - m);
    float ssum = e;
#pragma unroll
    for (int o = 8; o; o >>= 1) ssum += __shfl_xor_sync(0xffffffffu, ssum, o, 16);
    out[node * 16 + c] = acc - m - logf(ssum);
}

// ---------------- launch ----------------------------------------------------
extern "C" void kernel_launch(void* const* d_in, const int* in_sizes, int n_in,
                              void* d_out, int out_size) {
    const float* feat = (const float*)d_in[0];
    const float* ew   = (const float*)d_in[1];
    const int*   src  = (const int*)  d_in[2];
    const int*   dst  = (const int*)  d_in[3];
    const float* W0   = (const float*)d_in[4];
    const float* b0   = (const float*)d_in[5];
    const float* W1   = (const float*)d_in[6];
    const float* b1   = (const float*)d_in[7];
    const float* W2   = (const float*)d_in[8];
    const float* b2   = (const float*)d_in[9];
    float* out = (float*)d_out;

    // layer dropout keys: fold_in(key(42), l) = threefry((0,42), (0,l))
    uint32_t lk0[3], lk1[3];
    for (int l = 0; l < 3; l++) {
        uint32_t a = 0u, b = (uint32_t)l;
        tf2x32(0u, 42u, a, b);
        lk0[l] = a; lk1[l] = b;
    }

    const int TPB = 256;
    int nb_n = (NN + TPB - 1) / TPB;
    int nb_e = (NE + TPB - 1) / TPB;
    int nb_p = (ST / 4 + TPB - 1) / TPB;   // 1,200,000 / 256
    int nb_a = (NN * 32 + TPB - 1) / TPB;  // warp per node -> 6250
    int nb_g = (NN + 63) / 64;             // 782
    int nb_z = (NN + 15) / 16;             // 3125
    int nb_a16 = (NN * 16 + TPB - 1) / TPB;// 3125

    // graph preprocessing (reused by all 3 layers)
    k_zero<<<nb_n, TPB>>>();
    k_count<<<nb_e, TPB>>>(src, dst);
    k_scanA<<<SCB, 256>>>();   // also computes iO/iI
    k_scanB<<<1, 1>>>();
    k_scanC<<<SCB, 256>>>();
    k_fill<<<nb_e, TPB>>>(src, dst, ew);

    // layer 0: dropout(feat) -> X ; agg ; gemm(W0) with fused dropout(key 1)
    k_prep<<<nb_p, TPB>>>(feat, lk0[0], lk1[0]);
    k_agg<<<nb_a, TPB>>>();
    k_gemm96<<<nb_g, TPB>>>(W0, b0, lk0[1], lk1[1]);
    // layer 1: agg ; gemm(W1) with fused dropout(key 2)
    k_agg<<<nb_a, TPB>>>();
    k_gemm96<<<nb_g, TPB>>>(W1, b1, lk0[2], lk1[2]);
    // layer 2 (head, reordered): Z = X @ W2 first, then 16-dim aggregation
    k_gemmZ<<<nb_z, TPB>>>(W2);
    k_agg16<<<nb_a16, TPB>>>(b2, out);
}

// round 17
// speedup vs baseline: 1.5480x; 1.0375x over previous
#include <cuda_runtime.h>
#include <cuda_fp16.h>
#include <stdint.h>

#define NN 50000
#define NE 800000
#define D  96
#define NC 16
#define ST (NN*D)        // 4,800,000
#define SCB 49           // scan blocks: 49 * 1024 >= NN

// ---------------- scratch (static device globals; no allocation) ----------
__device__ __align__(16) __half g_Xh[ST]; // dropout-masked layer input (fp16)
__device__ __align__(16) float g_Y[ST];   // aggregation output (iI applied)
__device__ __align__(16) float g_Z[NN * NC]; // X @ W2 (pre-aggregation head)
__device__ int   g_cO[NN];
__device__ int   g_cI[NN];
__device__ float g_iO[NN];
__device__ float g_iI[NN];
__device__ int   g_off[NN + 1];           // CSR offsets by dst
__device__ int   g_cur[NN];               // fill cursors
__device__ int   g_part[SCB];             // per-block totals
__device__ int   g_partx[SCB];            // exclusive scan of totals
__device__ uint2 g_ep[NE];                // packed (src, folded-weight-bits) by dst

// ---------------- threefry2x32-20 (matches JAX) ----------------------------
__device__ __host__ __forceinline__ void tf2x32(uint32_t k0, uint32_t k1,
                                                uint32_t& x0, uint32_t& x1) {
    uint32_t k2 = k0 ^ k1 ^ 0x1BD11BDAu;
    x0 += k0; x1 += k1;
#define TF_R(r) { x0 += x1; x1 = (x1 << (r)) | (x1 >> (32 - (r))); x1 ^= x0; }
    TF_R(13) TF_R(15) TF_R(26) TF_R(6)   x0 += k1; x1 += k2 + 1u;
    TF_R(17) TF_R(29) TF_R(16) TF_R(24)  x0 += k2; x1 += k0 + 2u;
    TF_R(13) TF_R(15) TF_R(26) TF_R(6)   x0 += k0; x1 += k1 + 3u;
    TF_R(17) TF_R(29) TF_R(16) TF_R(24)  x0 += k1; x1 += k2 + 4u;
    TF_R(13) TF_R(15) TF_R(26) TF_R(6)   x0 += k2; x1 += k0 + 5u;
#undef TF_R
}

// keep ⇔ msb(out0 ^ out1) == 0, counter (0, idx)  [JAX partitionable threefry]
__device__ __forceinline__ bool keep_bit(uint32_t k0, uint32_t k1, uint32_t idx) {
    uint32_t x0 = 0u, x1 = idx;
    tf2x32(k0, k1, x0, x1);
    return (x0 ^ x1) < 0x80000000u;
}

// ---------------- degree kernels -------------------------------------------
__global__ void k_zero() {
    int i = blockIdx.x * blockDim.x + threadIdx.x;
    if (i < NN) { g_cO[i] = 0; g_cI[i] = 0; }
}

__global__ void k_count(const int* __restrict__ src, const int* __restrict__ dst) {
    int e = blockIdx.x * blockDim.x + threadIdx.x;
    if (e < NE) {
        atomicAdd(&g_cO[src[e]], 1);
        atomicAdd(&g_cI[dst[e]], 1);
    }
}

__global__ void k_fin() {
    int i = blockIdx.x * blockDim.x + threadIdx.x;
    if (i < NN) {
        g_iO[i] = rsqrtf((float)max(g_cO[i], 1));
        g_iI[i] = rsqrtf((float)max(g_cI[i], 1));
    }
}

// ---------------- CSR build: 3-phase multi-block scan -----------------------
__global__ void k_scanA() {
    __shared__ int sh[256];
    int t = threadIdx.x;
    int base = blockIdx.x * 1024 + t * 4;
    int v[4], s = 0;
#pragma unroll
    for (int j = 0; j < 4; j++) {
        v[j] = (base + j < NN) ? g_cI[base + j] : 0;
        s += v[j];
    }
    sh[t] = s;
    __syncthreads();
#pragma unroll
    for (int off = 1; off < 256; off <<= 1) {
        int x = (t >= off) ? sh[t - off] : 0;
        __syncthreads();
        sh[t] += x;
        __syncthreads();
    }
    int run = sh[t] - s;   // exclusive prefix within block
#pragma unroll
    for (int j = 0; j < 4; j++) {
        if (base + j < NN) g_off[base + j] = run;
        run += v[j];
    }
    if (t == 255) g_part[blockIdx.x] = sh[255];
}

// Parallel exclusive scan of the 49 block totals (1 block, 64 threads).
__global__ void k_scanB() {
    __shared__ int sh[64];
    int t = threadIdx.x;
    int v = (t < SCB) ? g_part[t] : 0;
    sh[t] = v;
    __syncthreads();
#pragma unroll
    for (int off = 1; off < 64; off <<= 1) {
        int x = (t >= off) ? sh[t - off] : 0;
        __syncthreads();
        sh[t] += x;
        __syncthreads();
    }
    if (t < SCB) g_partx[t] = sh[t] - v;   // exclusive
}

__global__ void k_scanC() {
    int t = threadIdx.x;
    int base = blockIdx.x * 1024 + t * 4;
    int add = g_partx[blockIdx.x];
#pragma unroll
    for (int j = 0; j < 4; j++) {
        int i = base + j;
        if (i < NN) {
            int o = g_off[i] + add;
            g_off[i] = o;
            g_cur[i] = o;
        }
    }
    if (blockIdx.x == 0 && t == 0) g_off[NN] = NE;
}

// Fold dropout 1/(1-p)=2 and D_out^-1/2 of the source into the edge weight.
__global__ void k_fill(const int* __restrict__ src, const int* __restrict__ dst,
                       const float* __restrict__ ew) {
    int e = blockIdx.x * blockDim.x + threadIdx.x;
    if (e < NE) {
        int d = dst[e];
        int s = src[e];
        float w = ew[e] * 2.0f * g_iO[s];
        int slot = atomicAdd(&g_cur[d], 1);
        g_ep[slot] = make_uint2((uint32_t)s, __float_as_uint(w));
    }
}

// ---------------- layer-0 dropout on the input features -> fp16 -------------
__global__ void k_prep(const float* __restrict__ hin, uint32_t k0, uint32_t k1) {
    int t = blockIdx.x * blockDim.x + threadIdx.x;
    if (t >= ST / 4) return;
    int j = t * 4;
    float4 a = *(const float4*)(hin + j);
    float v[4] = {a.x, a.y, a.z, a.w};
#pragma unroll
    for (int i = 0; i < 4; i++) {
        if (!keep_bit(k0, k1, (uint32_t)(j + i))) v[i] = 0.0f;
    }
    __half2 h0 = __floats2half2_rn(v[0], v[1]);
    __half2 h1 = __floats2half2_rn(v[2], v[3]);
    uint2 pk;
    pk.x = *(uint32_t*)&h0;
    pk.y = *(uint32_t*)&h1;
    *(uint2*)(g_Xh + j) = pk;
}

// ---------------- aggregation: warp per dst node (fp16 gather + HFMA2) ------
// Row = 48 uint32 words. Per 2 edges: 3 fully-active warp loads. Lane L owns
// word L (accA) and word 32+(L&15) (accB, combined by shuffle at the end).
__global__ void k_agg() {
    int warp = (blockIdx.x * blockDim.x + threadIdx.x) >> 5;
    if (warp >= NN) return;
    int lane = threadIdx.x & 31;
    int l16 = lane & 15;
    bool lo = lane < 16;
    const uint32_t* X32 = (const uint32_t*)g_Xh;   // 48 words per row
    int beg = g_off[warp], end = g_off[warp + 1];
    __half2 accA = __float2half2_rn(0.f);
    __half2 accB = __float2half2_rn(0.f);
    int i = beg;
    for (; i + 2 <= end; i += 2) {
        uint2 p0 = g_ep[i], p1 = g_ep[i + 1];
        int r0 = (int)p0.x * 48, r1 = (int)p1.x * 48;
        __half2 w0 = __float2half2_rn(__uint_as_float(p0.y));
        __half2 w1 = __float2half2_rn(__uint_as_float(p1.y));
        uint32_t uA0 = X32[r0 + lane];                   // edge0 words 0-31
        uint32_t uB  = X32[(lo ? r0 : r1) + 32 + l16];   // words 32-47 split
        uint32_t uA1 = X32[r1 + lane];                   // edge1 words 0-31
        accA = __hfma2(w0, *(__half2*)&uA0, accA);
        accB = __hfma2(lo ? w0 : w1, *(__half2*)&uB, accB);
        accA = __hfma2(w1, *(__half2*)&uA1, accA);
    }
    if (i < end) {
        uint2 p = g_ep[i];
        int r = (int)p.x * 48;
        __half2 w = __float2half2_rn(__uint_as_float(p.y));
        uint32_t uA = X32[r + lane];
        accA = __hfma2(w, *(__half2*)&uA, accA);
        if (lo) {
            uint32_t uB = X32[r + 32 + l16];
            accB = __hfma2(w, *(__half2*)&uB, accB);
        }
    }
    float2 fA = __half22float2(accA);
    float2 fB = __half22float2(accB);
    fB.x += __shfl_xor_sync(0xffffffffu, fB.x, 16);
    fB.y += __shfl_xor_sync(0xffffffffu, fB.y, 16);
    float sc = g_iI[warp];
    float2* y = (float2*)(g_Y + warp * D);   // 48 float2 per row
    y[lane] = make_float2(fA.x * sc, fA.y * sc);
    if (lo) y[32 + l16] = make_float2(fB.x * sc, fB.y * sc);
}

// ------- GEMM 96x96 + bias + relu + FUSED next-layer dropout -> fp16 X ------
__global__ void k_gemm96(const float* __restrict__ W, const float* __restrict__ b,
                         uint32_t k0, uint32_t k1) {
    __shared__ float rows[8][8][96];   // 24.5 KB
    int tid = threadIdx.x, wid = tid >> 5, lane = tid & 31;
    int base = blockIdx.x * 64 + wid * 8;
#pragma unroll
    for (int j = 0; j < 8; j++) {
        int n = base + j;
        if (n < NN) {
            const float* yr = g_Y + n * 96;
            rows[wid][j][lane]      = yr[lane];
            rows[wid][j][lane + 32] = yr[lane + 32];
            rows[wid][j][lane + 64] = yr[lane + 64];
        }
    }
    float b0 = __ldg(b + lane), b1 = __ldg(b + lane + 32), b2 = __ldg(b + lane + 64);
    float acc[8][3];
#pragma unroll
    for (int j = 0; j < 8; j++) { acc[j][0] = b0; acc[j][1] = b1; acc[j][2] = b2; }
    __syncwarp();
#pragma unroll 4
    for (int k = 0; k < 96; k++) {
        float w0 = __ldg(W + k * 96 + lane);
        float w1 = __ldg(W + k * 96 + lane + 32);
        float w2 = __ldg(W + k * 96 + lane + 64);
#pragma unroll
        for (int j = 0; j < 8; j++) {
            float r = rows[wid][j][k];
            acc[j][0] += r * w0; acc[j][1] += r * w1; acc[j][2] += r * w2;
        }
    }
#pragma unroll
    for (int j = 0; j < 8; j++) {
        int n = base + j;
        if (n < NN) {
            __half* o = g_Xh + n * 96;
#pragma unroll
            for (int c = 0; c < 3; c++) {
                int col = lane + c * 32;
                float val = fmaxf(acc[j][c], 0.f);
                bool kp = keep_bit(k0, k1, (uint32_t)(n * 96 + col));
                o[col] = __float2half_rn(kp ? val : 0.0f);
            }
        }
    }
}

// ---------------- head GEMM first: Z = X @ W2 (96 -> 16, no bias) -----------
__global__ void k_gemmZ(const float* __restrict__ W) {
    __shared__ float Ws[96 * 16];
    __shared__ float rows[8][2][96];
    int tid = threadIdx.x, wid = tid >> 5, lane = tid & 31;
    for (int i = tid; i < 96 * 16; i += 256) Ws[i] = W[i];
    int h = lane >> 4, c = lane & 15;
    int n = blockIdx.x * 16 + wid * 2 + h;
    const __half* xr = g_Xh + n * 96;
    for (int k = c; k < 96; k += 16) rows[wid][h][k] = __half2float(xr[k]);
    __syncthreads();
    float acc = 0.f;
#pragma unroll 8
    for (int k = 0; k < 96; k++) acc += rows[wid][h][k] * Ws[k * 16 + c];
    g_Z[n * 16 + c] = acc;
}

// ------- final aggregation in 16-dim + iI + bias + log_softmax --------------
__global__ void k_agg16(const float* __restrict__ b, float* __restrict__ out) {
    int gtid = blockIdx.x * blockDim.x + threadIdx.x;
    int node = gtid >> 4;
    if (node >= NN) return;
    int c = gtid & 15;
    int beg = g_off[node], end = g_off[node + 1];
    float acc = 0.f;
    int i = beg;
    for (; i + 2 <= end; i += 2) {
        uint2 p0 = g_ep[i], p1 = g_ep[i + 1];
        float z0 = g_Z[(int)p0.x * 16 + c];
        float z1 = g_Z[(int)p1.x * 16 + c];
        acc += __uint_as_float(p0.y) * z0;
        acc += __uint_as_float(p1.y) * z1;
    }
    if (i < end) {
        uint2 p = g_ep[i];
        acc += __uint_as_float(p.y) * g_Z[(int)p.x * 16 + c];
    }
    acc = acc * g_iI[node] + __ldg(b + c);
    float m = acc;
#pragma unroll
    for (int o = 8; o; o >>= 1) m = fmaxf(m, __shfl_xor_sync(0xffffffffu, m, o, 16));
    float e = expf(acc - m);
    float ssum = e;
#pragma unroll
    for (int o = 8; o; o >>= 1) ssum += __shfl_xor_sync(0xffffffffu, ssum, o, 16);
    out[node * 16 + c] = acc - m - logf(ssum);
}

// ---------------- launch ----------------------------------------------------
extern "C" void kernel_launch(void* const* d_in, const int* in_sizes, int n_in,
                              void* d_out, int out_size) {
    const float* feat = (const float*)d_in[0];
    const float* ew   = (const float*)d_in[1];
    const int*   src  = (const int*)  d_in[2];
    const int*   dst  = (const int*)  d_in[3];
    const float* W0   = (const float*)d_in[4];
    const float* b0   = (const float*)d_in[5];
    const float* W1   = (const float*)d_in[6];
    const float* b1   = (const float*)d_in[7];
    const float* W2   = (const float*)d_in[8];
    const float* b2   = (const float*)d_in[9];
    float* out = (float*)d_out;

    // layer dropout keys: fold_in(key(42), l) = threefry((0,42), (0,l))
    uint32_t lk0[3], lk1[3];
    for (int l = 0; l < 3; l++) {
        uint32_t a = 0u, b = (uint32_t)l;
        tf2x32(0u, 42u, a, b);
        lk0[l] = a; lk1[l] = b;
    }

    const int TPB = 256;
    int nb_n = (NN + TPB - 1) / TPB;
    int nb_e = (NE + TPB - 1) / TPB;
    int nb_p = (ST / 4 + TPB - 1) / TPB;   // 1,200,000 / 256
    int nb_a = (NN * 32 + TPB - 1) / TPB;  // warp per node -> 6250
    int nb_g = (NN + 63) / 64;             // 782
    int nb_z = (NN + 15) / 16;             // 3125
    int nb_a16 = (NN * 16 + TPB - 1) / TPB;// 3125

    // graph preprocessing (reused by all 3 layers)
    k_zero<<<nb_n, TPB>>>();
    k_count<<<nb_e, TPB>>>(src, dst);
    k_fin<<<nb_n, TPB>>>();
    k_scanA<<<SCB, 256>>>();
    k_scanB<<<1, 64>>>();
    k_scanC<<<SCB, 256>>>();
    k_fill<<<nb_e, TPB>>>(src, dst, ew);

    // layer 0: dropout(feat) -> X ; agg ; gemm(W0) with fused dropout(key 1)
    k_prep<<<nb_p, TPB>>>(feat, lk0[0], lk1[0]);
    k_agg<<<nb_a, TPB>>>();
    k_gemm96<<<nb_g, TPB>>>(W0, b0, lk0[1], lk1[1]);
    // layer 1: agg ; gemm(W1) with fused dropout(key 2)
    k_agg<<<nb_a, TPB>>>();
    k_gemm96<<<nb_g, TPB>>>(W1, b1, lk0[2], lk1[2]);
    // layer 2 (head, reordered): Z = X @ W2 first, then 16-dim aggregation
    k_gemmZ<<<nb_z, TPB>>>(W2);
    k_agg16<<<nb_a16, TPB>>>(b2, out);
}